// round 1
// baseline (speedup 1.0000x reference)
#include <cuda_runtime.h>
#include <math.h>

// Problem constants
#define B_   32
#define C_   512
#define HW_  3136          // 56*56
#define N_   27
#define NPIX (B_*HW_)      // 100352 pixels
#define CCHUNK  128        // channels per smem tile
#define NCHUNKS (C_/CCHUNK)
#define ROWPAD  56         // floats per channel row in smem: 27 duplicated pairs = 54, pad to 56 (224B, 16B aligned)

// Scratch (no device allocation allowed)
__device__ float  g_cl[N_ * C_];   // normalized clusters, [n][c]
__device__ double g_loss;

// ---------------------------------------------------------------------------
// packed f32x2 helpers (sm_103a)
// ---------------------------------------------------------------------------
__device__ __forceinline__ unsigned long long packf2(float x, float y) {
    unsigned long long r;
    asm("mov.b64 %0, {%1, %2};" : "=l"(r) : "f"(x), "f"(y));
    return r;
}
__device__ __forceinline__ void unpackf2(unsigned long long d, float& x, float& y) {
    asm("mov.b64 {%0, %1}, %2;" : "=f"(x), "=f"(y) : "l"(d));
}
#define FMA2(d, a, b) asm("fma.rn.f32x2 %0, %1, %2, %0;" : "+l"(d) : "l"(a), "l"(b))

// ---------------------------------------------------------------------------
// Kernel 0: normalize clusters rows (27 blocks x 128 threads), zero loss accum
// ---------------------------------------------------------------------------
__global__ void prep_kernel(const float* __restrict__ clusters) {
    int n   = blockIdx.x;
    int tid = threadIdx.x;

    float p = 0.f;
    for (int c = tid; c < C_; c += 128) {
        float v = clusters[n * C_ + c];
        p += v * v;
    }
    #pragma unroll
    for (int o = 16; o; o >>= 1) p += __shfl_xor_sync(0xffffffffu, p, o);

    __shared__ float ws[4];
    if ((tid & 31) == 0) ws[tid >> 5] = p;
    __syncthreads();
    float tot = ws[0] + ws[1] + ws[2] + ws[3];
    float inv = 1.f / fmaxf(sqrtf(tot), 1e-12f);

    for (int c = tid; c < C_; c += 128)
        g_cl[n * C_ + c] = clusters[n * C_ + c] * inv;

    if (n == 0 && tid == 0) g_loss = 0.0;
}

// ---------------------------------------------------------------------------
// Kernel 1: main fused kernel.
// Each thread owns 2 adjacent pixels (hw, hw+1)  -> float2 loads, f32x2 math.
// 392 blocks x 128 threads, each block = 256 pixels.
// Clusters staged in smem duplicated {c,c} so LDS.128 delivers two f32x2
// operands directly.
// ---------------------------------------------------------------------------
__global__ void __launch_bounds__(128)
main_kernel(const float* __restrict__ x, float* __restrict__ out, int probs_off) {
    __shared__ __align__(16) float sCl[CCHUNK * ROWPAD];

    int pairIdx = blockIdx.x * 128 + threadIdx.x;
    int p0 = pairIdx * 2;                 // first pixel; HW_ even -> pair never crosses b
    int b  = p0 / HW_;
    int hw = p0 - b * HW_;

    const float2* xp = reinterpret_cast<const float2*>(x)
                     + ((size_t)b * C_ * HW_ + hw) / 2;   // both terms even

    unsigned long long acc[N_];
    unsigned long long ssq = 0ull;
    #pragma unroll
    for (int n = 0; n < N_; ++n) acc[n] = 0ull;

    for (int ch = 0; ch < NCHUNKS; ++ch) {
        __syncthreads();   // protect prior-chunk smem reads
        // Fill smem tile: CCHUNK==blockDim, each thread handles channel 'tid'
        {
            int cc = threadIdx.x;
            int cbase = ch * CCHUNK + cc;
            #pragma unroll
            for (int n = 0; n < N_; ++n) {
                float v = g_cl[n * C_ + cbase];
                sCl[cc * ROWPAD + 2 * n]     = v;
                sCl[cc * ROWPAD + 2 * n + 1] = v;
            }
        }
        __syncthreads();

        const float2* xc = xp + (size_t)ch * CCHUNK * (HW_ / 2);
        #pragma unroll 2
        for (int cc = 0; cc < CCHUNK; ++cc) {
            float2 xv = xc[(size_t)cc * (HW_ / 2)];
            unsigned long long xv2 = packf2(xv.x, xv.y);
            FMA2(ssq, xv2, xv2);

            const double2* crow = reinterpret_cast<const double2*>(&sCl[cc * ROWPAD]);
            #pragma unroll
            for (int j = 0; j < 13; ++j) {
                double2 d = crow[j];                     // LDS.128 broadcast: {c2j,c2j, c2j+1,c2j+1}
                unsigned long long c0 = __double_as_longlong(d.x);
                unsigned long long c1 = __double_as_longlong(d.y);
                FMA2(acc[2 * j],     xv2, c0);
                FMA2(acc[2 * j + 1], xv2, c1);
            }
            unsigned long long ct = __double_as_longlong(
                *reinterpret_cast<const double*>(&sCl[cc * ROWPAD + 52]));
            FMA2(acc[26], xv2, ct);
        }
    }

    // ---------------- epilogue: normalize, softmax, store, loss ----------------
    float q0, q1;
    unpackf2(ssq, q0, q1);
    float inv0 = 1.f / fmaxf(sqrtf(q0), 1e-12f);
    float inv1 = 1.f / fmaxf(sqrtf(q1), 1e-12f);

    float s0[N_], s1[N_];
    float m0 = -1e30f, m1 = -1e30f;
    #pragma unroll
    for (int n = 0; n < N_; ++n) {
        float a0, a1;
        unpackf2(acc[n], a0, a1);
        s0[n] = a0 * inv0;
        s1[n] = a1 * inv1;
        m0 = fmaxf(m0, s0[n]);
        m1 = fmaxf(m1, s1[n]);
    }
    float sum0 = 0.f, sum1 = 0.f;
    #pragma unroll
    for (int n = 0; n < N_; ++n) {
        sum0 += __expf(2.f * (s0[n] - m0));
        sum1 += __expf(2.f * (s1[n] - m1));
    }
    float r0 = 1.f / sum0, r1 = 1.f / sum1;

    float* po = out + probs_off + (size_t)b * N_ * HW_ + hw;
    float lp = 0.f;
    #pragma unroll
    for (int n = 0; n < N_; ++n) {
        float pv0 = __expf(2.f * (s0[n] - m0)) * r0;   // recompute exp -> fewer live regs
        float pv1 = __expf(2.f * (s1[n] - m1)) * r1;
        po[(size_t)n * HW_]     = pv0;
        po[(size_t)n * HW_ + 1] = pv1;
        lp += pv0 * s0[n] + pv1 * s1[n];
    }

    // loss partial: warp reduce + one atomic per warp
    #pragma unroll
    for (int o = 16; o; o >>= 1) lp += __shfl_xor_sync(0xffffffffu, lp, o);
    if ((threadIdx.x & 31) == 0) atomicAdd(&g_loss, (double)lp);
}

// ---------------------------------------------------------------------------
// Kernel 2: finalize loss scalar
// ---------------------------------------------------------------------------
__global__ void final_kernel(float* __restrict__ out, int write_loss) {
    if (write_loss) out[0] = (float)(-g_loss / (double)NPIX);
}

// ---------------------------------------------------------------------------
extern "C" void kernel_launch(void* const* d_in, const int* in_sizes, int n_in,
                              void* d_out, int out_size) {
    // Disambiguate input order by element counts
    const float* x        = (const float*)d_in[0];
    const float* clusters = (const float*)d_in[1];
    if (in_sizes[0] == N_ * C_) {            // clusters arrived first
        x        = (const float*)d_in[1];
        clusters = (const float*)d_in[0];
    }
    float* out = (float*)d_out;

    // out = [loss, probs...] if out_size has one extra element; else probs only
    int probs_off  = out_size - (B_ * N_ * HW_);
    if (probs_off < 0) probs_off = 0;
    int write_loss = (probs_off >= 1) ? 1 : 0;

    prep_kernel<<<N_, 128>>>(clusters);
    main_kernel<<<(NPIX / 2) / 128, 128>>>(x, out, probs_off);
    final_kernel<<<1, 1>>>(out, write_loss);
}

// round 2
// speedup vs baseline: 1.4938x; 1.4938x over previous
#include <cuda_runtime.h>
#include <math.h>

// Problem constants
#define B_   32
#define C_   512
#define HW_  3136          // 56*56
#define N_   27
#define NPIX (B_*HW_)      // 100352 pixels
#define CCHUNK  128        // channels per smem tile
#define NCHUNKS (C_/CCHUNK)
#define ROWPAD  56         // floats per channel row: 27 duplicated pairs = 54, pad to 56 (224B)
#define PF     8           // prefetch depth (channels per batch)
#define NBATCH (CCHUNK/PF) // 16 batches per chunk
#define F2STRIDE (HW_/2)   // float2 stride between channels = 1568

// Scratch (no device allocation allowed)
__device__ float    g_cl[N_ * C_];   // normalized clusters, [n][c]
__device__ double   g_loss;
__device__ unsigned g_done;          // block completion ticket (reset by last block)

// ---------------------------------------------------------------------------
// packed f32x2 helpers (sm_103a)
// ---------------------------------------------------------------------------
__device__ __forceinline__ unsigned long long packf2(float x, float y) {
    unsigned long long r;
    asm("mov.b64 %0, {%1, %2};" : "=l"(r) : "f"(x), "f"(y));
    return r;
}
__device__ __forceinline__ void unpackf2(unsigned long long d, float& x, float& y) {
    asm("mov.b64 {%0, %1}, %2;" : "=f"(x), "=f"(y) : "l"(d));
}
#define FMA2(d, a, b) asm("fma.rn.f32x2 %0, %1, %2, %0;" : "+l"(d) : "l"(a), "l"(b))

// ---------------------------------------------------------------------------
// Kernel 0: normalize cluster rows (27 blocks x 512 threads), zero accumulators
// ---------------------------------------------------------------------------
__global__ void prep_kernel(const float* __restrict__ clusters) {
    int n   = blockIdx.x;
    int tid = threadIdx.x;

    float v = clusters[n * C_ + tid];       // 512 threads = C_ elements
    float p = v * v;
    #pragma unroll
    for (int o = 16; o; o >>= 1) p += __shfl_xor_sync(0xffffffffu, p, o);

    __shared__ float ws[16];
    if ((tid & 31) == 0) ws[tid >> 5] = p;
    __syncthreads();
    float tot = 0.f;
    #pragma unroll
    for (int w = 0; w < 16; ++w) tot += ws[w];
    float inv = 1.f / fmaxf(sqrtf(tot), 1e-12f);

    g_cl[n * C_ + tid] = v * inv;

    if (n == 0 && tid == 0) { g_loss = 0.0; }
}

// ---------------------------------------------------------------------------
// Kernel 1: main fused kernel (dots + normalize + softmax + probs + loss).
// Each thread owns 2 adjacent pixels -> float2 loads, f32x2 math.
// 392 blocks x 128 threads. Register double-buffered prefetch of PF=8
// channels keeps MLP ~8/warp. Clusters staged in smem duplicated {c,c} so
// one LDS.128 yields two ready f32x2 operands.
// ---------------------------------------------------------------------------
__global__ void __launch_bounds__(128, 3)
main_kernel(const float* __restrict__ x, float* __restrict__ out,
            int probs_off, int write_loss, int nblocks) {
    __shared__ __align__(16) float sCl[CCHUNK * ROWPAD];

    int pairIdx = blockIdx.x * 128 + threadIdx.x;
    int p0 = pairIdx * 2;                 // HW_ even -> pair never crosses batch b
    int b  = p0 / HW_;
    int hw = p0 - b * HW_;

    const float2* xp = reinterpret_cast<const float2*>(x)
                     + ((size_t)b * C_ * HW_ + hw) / 2;

    unsigned long long acc[N_];
    unsigned long long ssq = 0ull;
    #pragma unroll
    for (int n = 0; n < N_; ++n) acc[n] = 0ull;

    float2 bufA[PF], bufB[PF];

    for (int ch = 0; ch < NCHUNKS; ++ch) {
        __syncthreads();   // protect prior-chunk smem reads
        {   // fill smem tile: thread tid owns channel tid of the chunk
            int cc = threadIdx.x;
            int cbase = ch * CCHUNK + cc;
            #pragma unroll
            for (int n = 0; n < N_; ++n) {
                float v = g_cl[n * C_ + cbase];
                sCl[cc * ROWPAD + 2 * n]     = v;
                sCl[cc * ROWPAD + 2 * n + 1] = v;
            }
        }
        __syncthreads();

        const float2* xc = xp + (size_t)ch * CCHUNK * F2STRIDE;

        // prologue: prefetch batch 0
        #pragma unroll
        for (int k = 0; k < PF; ++k) bufA[k] = xc[k * F2STRIDE];

        #pragma unroll 1
        for (int bt = 0; bt < NBATCH; bt += 2) {
            // prefetch batch bt+1 (always in range: NBATCH even)
            {
                const float2* xb = xc + (size_t)(bt + 1) * PF * F2STRIDE;
                #pragma unroll
                for (int k = 0; k < PF; ++k) bufB[k] = xb[k * F2STRIDE];
            }
            // compute batch bt from bufA
            #pragma unroll
            for (int k = 0; k < PF; ++k) {
                unsigned long long xv2 = packf2(bufA[k].x, bufA[k].y);
                FMA2(ssq, xv2, xv2);
                const float* row = &sCl[(bt * PF + k) * ROWPAD];
                const double2* crow = reinterpret_cast<const double2*>(row);
                #pragma unroll
                for (int j = 0; j < 13; ++j) {
                    double2 d = crow[j];
                    FMA2(acc[2 * j],     xv2, __double_as_longlong(d.x));
                    FMA2(acc[2 * j + 1], xv2, __double_as_longlong(d.y));
                }
                unsigned long long ct = __double_as_longlong(
                    *reinterpret_cast<const double*>(row + 52));
                FMA2(acc[26], xv2, ct);
            }
            // prefetch batch bt+2 (guarded on last pair)
            if (bt + 2 < NBATCH) {
                const float2* xb = xc + (size_t)(bt + 2) * PF * F2STRIDE;
                #pragma unroll
                for (int k = 0; k < PF; ++k) bufA[k] = xb[k * F2STRIDE];
            }
            // compute batch bt+1 from bufB
            #pragma unroll
            for (int k = 0; k < PF; ++k) {
                unsigned long long xv2 = packf2(bufB[k].x, bufB[k].y);
                FMA2(ssq, xv2, xv2);
                const float* row = &sCl[((bt + 1) * PF + k) * ROWPAD];
                const double2* crow = reinterpret_cast<const double2*>(row);
                #pragma unroll
                for (int j = 0; j < 13; ++j) {
                    double2 d = crow[j];
                    FMA2(acc[2 * j],     xv2, __double_as_longlong(d.x));
                    FMA2(acc[2 * j + 1], xv2, __double_as_longlong(d.y));
                }
                unsigned long long ct = __double_as_longlong(
                    *reinterpret_cast<const double*>(row + 52));
                FMA2(acc[26], xv2, ct);
            }
        }
    }

    // ---------------- epilogue: normalize, softmax, store, loss ----------------
    float q0, q1;
    unpackf2(ssq, q0, q1);
    float inv0 = 1.f / fmaxf(sqrtf(q0), 1e-12f);
    float inv1 = 1.f / fmaxf(sqrtf(q1), 1e-12f);

    float s0[N_], s1[N_];
    float m0 = -1e30f, m1 = -1e30f;
    #pragma unroll
    for (int n = 0; n < N_; ++n) {
        float a0, a1;
        unpackf2(acc[n], a0, a1);
        s0[n] = a0 * inv0;
        s1[n] = a1 * inv1;
        m0 = fmaxf(m0, s0[n]);
        m1 = fmaxf(m1, s1[n]);
    }
    float sum0 = 0.f, sum1 = 0.f;
    #pragma unroll
    for (int n = 0; n < N_; ++n) {
        sum0 += __expf(2.f * (s0[n] - m0));
        sum1 += __expf(2.f * (s1[n] - m1));
    }
    float r0 = 1.f / sum0, r1 = 1.f / sum1;

    float* po = out + probs_off + (size_t)b * N_ * HW_ + hw;
    float lp = 0.f;
    #pragma unroll
    for (int n = 0; n < N_; ++n) {
        float pv0 = __expf(2.f * (s0[n] - m0)) * r0;
        float pv1 = __expf(2.f * (s1[n] - m1)) * r1;
        po[(size_t)n * HW_]     = pv0;
        po[(size_t)n * HW_ + 1] = pv1;
        lp += pv0 * s0[n] + pv1 * s1[n];
    }

    // loss partial: warp reduce + one atomic per warp
    #pragma unroll
    for (int o = 16; o; o >>= 1) lp += __shfl_xor_sync(0xffffffffu, lp, o);
    if ((threadIdx.x & 31) == 0) atomicAdd(&g_loss, (double)lp);

    // last-block finalization (replaces separate final kernel)
    __shared__ unsigned s_last;
    __syncthreads();                       // all warps' g_loss atomics issued
    if (threadIdx.x == 0) {
        __threadfence();
        s_last = (atomicAdd(&g_done, 1u) == (unsigned)(nblocks - 1));
    }
    __syncthreads();
    if (s_last && threadIdx.x == 0) {
        double L = *(volatile double*)&g_loss;
        if (write_loss) out[0] = (float)(-L / (double)NPIX);
        g_done = 0u;                       // reset for next launch / graph replay
    }
}

// ---------------------------------------------------------------------------
extern "C" void kernel_launch(void* const* d_in, const int* in_sizes, int n_in,
                              void* d_out, int out_size) {
    const float* x        = (const float*)d_in[0];
    const float* clusters = (const float*)d_in[1];
    if (in_sizes[0] == N_ * C_) {            // clusters arrived first
        x        = (const float*)d_in[1];
        clusters = (const float*)d_in[0];
    }
    float* out = (float*)d_out;

    int probs_off  = out_size - (B_ * N_ * HW_);
    if (probs_off < 0) probs_off = 0;
    int write_loss = (probs_off >= 1) ? 1 : 0;

    int nblocks = (NPIX / 2) / 128;          // 392
    prep_kernel<<<N_, 512>>>(clusters);
    main_kernel<<<nblocks, 128>>>(x, out, probs_off, write_loss, nblocks);
}